// round 14
// baseline (speedup 1.0000x reference)
#include <cuda_runtime.h>
#include <math.h>

#define NROWS 16384
#define DDIM  256
#define KCODES 2048
#define CAP   32

typedef unsigned long long u64;

__device__ float g_repar[KCODES*DDIM];
__device__ float g_csq[KCODES];
__device__ float g_cden[KCODES];
__device__ float g_fn[NROWS];
__device__ float g_fden[NROWS];
__device__ int      g_ck[NROWS*CAP];
__device__ unsigned g_cb[NROWS*CAP];
__device__ int   g_ccnt[NROWS];
__device__ int   g_count[KCODES];                  // zeroed each call by k_prep block 2304
__device__ int   g_cmax_bits  = 0;                 // monotone max: replay-deterministic
__device__ int   g_fnmax_bits = 0;                 // monotone max: replay-deterministic
__device__ int   g_cdmin_bits = 0x7f800000;        // monotone min: replay-deterministic
__device__ double g_cos, g_commit, g_gap, g_cdsum; // zeroed each call by k_prep block 2304

// ---------- fast-math-immune fdlibm logf (<=1 ulp) ----------
__device__ __forceinline__ float logf_rn(float x) {
    int ix = __float_as_int(x);
    int k = (ix >> 23) - 127;
    int man = ix & 0x007fffff;
    int i = (man + 0x4afb20) & 0x800000;
    float m = __int_as_float(man | (i ^ 0x3f800000));
    k += (i >> 23);
    float f = __fadd_rn(m, -1.0f);
    float s = __fdiv_rn(f, __fadd_rn(2.0f, f));
    float dk = (float)k;
    float z = __fmul_rn(s, s);
    float w = __fmul_rn(z, z);
    float t1 = __fmul_rn(w, __fmaf_rn(w, 0.24279078841f, 0.40000972152f));
    float t2 = __fmul_rn(z, __fmaf_rn(w, 0.28498786688f, 0.66666662693f));
    float R = __fadd_rn(t2, t1);
    float hfsq = __fmul_rn(0.5f, __fmul_rn(f, f));
    float a = __fmaf_rn(s, __fadd_rn(hfsq, R), __fmul_rn(dk, 9.0580006145e-06f));
    float b = __fsub_rn(__fsub_rn(hfsq, a), f);
    return __fsub_rn(__fmul_rn(dk, 0.69313812256f), b);
}

// ---------- threefry2x32, key=(0,42), natural form ----------
__device__ __forceinline__ uint2 tf_0_42(unsigned x0, unsigned x1) {
    const unsigned ks0 = 0u, ks1 = 42u, ks2 = 0x1BD11BDAu ^ 42u;
    x0 += ks0; x1 += ks1;
#define TR(r) { x0 += x1; x1 = __funnelshift_l(x1, x1, r); x1 ^= x0; }
    TR(13) TR(15) TR(26) TR(6)   x0 += ks1; x1 += ks2 + 1u;
    TR(17) TR(29) TR(16) TR(24)  x0 += ks2; x1 += ks0 + 2u;
    TR(13) TR(15) TR(26) TR(6)   x0 += ks0; x1 += ks1 + 3u;
    TR(17) TR(29) TR(16) TR(24)  x0 += ks1; x1 += ks2 + 4u;
    TR(13) TR(15) TR(26) TR(6)   x0 += ks2; x1 += ks0 + 5u;
#undef TR
    return make_uint2(x0, x1);
}

// partitionable-mode word: ctr=(0,i), fold xor
__device__ __forceinline__ unsigned rbits(unsigned i) {
    uint2 r = tf_0_42(0u, i);
    return r.x ^ r.y;
}

__device__ __forceinline__ float gumbel_bits(unsigned bits) {
    const float TINY = 1.17549435082228751e-38f;
    float f = __fadd_rn(__uint_as_float((bits >> 9) | 0x3f800000u), -1.0f);
    float u = fmaxf(TINY, __fadd_rn(f, TINY));
    return -logf_rn(-logf_rn(u));
}

// ---------- f32x2 helpers ----------
__device__ __forceinline__ u64 pk2(float lo, float hi) {
    u64 r;
    asm("mov.b64 %0, {%1, %2};" : "=l"(r) : "r"(__float_as_uint(lo)), "r"(__float_as_uint(hi)));
    return r;
}
__device__ __forceinline__ void upk2(u64 v, float& lo, float& hi) {
    unsigned a, b;
    asm("mov.b64 {%0, %1}, %2;" : "=r"(a), "=r"(b) : "l"(v));
    lo = __uint_as_float(a); hi = __uint_as_float(b);
}
__device__ __forceinline__ u64 fma2(u64 a, u64 b, u64 c) {
    u64 d;
    asm("fma.rn.f32x2 %0, %1, %2, %3;" : "=l"(d) : "l"(a), "l"(b), "l"(c));
    return d;
}

// ---------- fused prep: [0,256) codes (warp/code), [256,2304) rows, 2304 = accum reset ----------
__global__ __launch_bounds__(256) void k_prep(const float* __restrict__ cb,
                                              const float* __restrict__ cm,
                                              const float* __restrict__ cs,
                                              const float* __restrict__ latent) {
    int b = blockIdx.x, t = threadIdx.x, lane = t & 31, wp = t >> 5;
    if (b < 256) {
        int w = b * 8 + wp;            // code id
        double s = 0.0;
        for (int d = lane; d < DDIM; d += 32) {
            float r = __fadd_rn(cm[d], __fmul_rn(cs[d], cb[w*DDIM + d]));
            g_repar[w*DDIM + d] = r;
            s += (double)r * (double)r;
        }
        for (int o = 16; o; o >>= 1) s += __shfl_xor_sync(0xffffffffu, s, o);
        if (lane == 0) {
            float c = (float)s;
            g_csq[w] = c;
            g_cden[w] = fmaxf(__fsqrt_rn(c), 1e-12f);
            atomicMax(&g_cmax_bits, __float_as_int(c));
        }
    } else if (b < 2304) {
        int w = (b - 256) * 8 + wp;    // row id
        double s = 0.0;
        for (int d = lane; d < DDIM; d += 32) {
            float f = latent[w*DDIM + d];
            s += (double)f * (double)f;
        }
        for (int o = 16; o; o >>= 1) s += __shfl_xor_sync(0xffffffffu, s, o);
        if (lane == 0) {
            float v = (float)s;
            g_fn[w] = v;
            g_fden[w] = fmaxf(__fsqrt_rn(v), 1e-12f);
            atomicMax(&g_fnmax_bits, __float_as_int(v));
        }
    } else {
        for (int k = t; k < KCODES; k += 256) g_count[k] = 0;
        if (t == 0) { g_cos = 0.0; g_commit = 0.0; g_gap = 0.0; g_cdsum = 0.0; }
    }
}

// ---------- gumbel candidates: one CTA per row, bits-domain threshold ----------
__global__ __launch_bounds__(256) void k_cand() {
    __shared__ unsigned sM[8];
    __shared__ unsigned thr_s;
    __shared__ int cnt_s;
    int t = threadIdx.x;
    unsigned n = blockIdx.x;
    unsigned base = n * 2048u;
    unsigned bits[8]; unsigned m = 0;
#pragma unroll
    for (int j = 0; j < 8; j++) {
        bits[j] = rbits(base + (unsigned)t * 8u + (unsigned)j);
        m = max(m, bits[j]);
    }
    for (int o = 16; o; o >>= 1) m = max(m, __shfl_xor_sync(0xffffffffu, m, o));
    if ((t & 31) == 0) sM[t >> 5] = m;
    __syncthreads();
    if (t == 0) {
        unsigned mb = sM[0];
#pragma unroll
        for (int i = 1; i < 8; i++) mb = max(mb, sM[i]);
        float gmax = gumbel_bits(mb);
        float csqmax = __int_as_float(g_cmax_bits);
        float fnmax  = __int_as_float(g_fnmax_bits);
        float DELTA = 4.0f*__fsqrt_rn(fnmax)*__fsqrt_rn(csqmax) + csqmax + 2e-3f;
        float thr = gmax - DELTA;
        float u_thr = __expf(-__expf(-thr));
        int mant = (int)floorf(u_thr * 8388608.0f) - 64;
        thr_s = (mant < 0) ? 0u : ((unsigned)mant << 9);
        cnt_s = 0;
    }
    __syncthreads();
    unsigned thr = thr_s;
#pragma unroll
    for (int j = 0; j < 8; j++) {
        if (bits[j] >= thr) {
            int pos = atomicAdd(&cnt_s, 1);
            if (pos < CAP) { g_ck[n*CAP+pos] = t*8+j; g_cb[n*CAP+pos] = bits[j]; }
        }
    }
    __syncthreads();
    if (t == 0) g_ccnt[n] = cnt_s;
}

// ---------- resolve + fused epilogue (warp per row) ----------
__global__ __launch_bounds__(256) void k_resolve(const float* __restrict__ latent,
                                                 float* __restrict__ outQ,
                                                 float* __restrict__ outIdx) {
    __shared__ double shc[8], shm[8], shg[8];
    int t = threadIdx.x, lane = t & 31, w = t >> 5;
    int n = blockIdx.x * 8 + w;
    const float4* L4 = (const float4*)latent;
    float4 fa = L4[n*64 + lane*2], fb = L4[n*64 + lane*2 + 1];
    float f[8] = {fa.x, fa.y, fa.z, fa.w, fb.x, fb.y, fb.z, fb.w};
    float fn = g_fn[n];
    int cnt = g_ccnt[n];
    float bestS = -INFINITY; int bestK = 0x7fffffff;
    if (cnt <= CAP) {
        for (int j = 0; j < cnt; j++) {
            int k = g_ck[n*CAP + j];
            float g = gumbel_bits(g_cb[n*CAP + j]);
            const float4* R4 = (const float4*)(g_repar + k*DDIM);
            float4 ca = __ldg(&R4[lane*2]), cb4 = __ldg(&R4[lane*2 + 1]);
            float dot = 0.0f;
            dot = __fmaf_rn(f[0], ca.x, dot);  dot = __fmaf_rn(f[1], ca.y, dot);
            dot = __fmaf_rn(f[2], ca.z, dot);  dot = __fmaf_rn(f[3], ca.w, dot);
            dot = __fmaf_rn(f[4], cb4.x, dot); dot = __fmaf_rn(f[5], cb4.y, dot);
            dot = __fmaf_rn(f[6], cb4.z, dot); dot = __fmaf_rn(f[7], cb4.w, dot);
            for (int o = 16; o; o >>= 1) dot = __fadd_rn(dot, __shfl_xor_sync(0xffffffffu, dot, o));
            float d = __fadd_rn(__fsub_rn(fn, 2.0f*dot), g_csq[k]);
            float s = __fsub_rn(g, d);
            if (s > bestS || (s == bestS && k < bestK)) { bestS = s; bestK = k; }
        }
    } else {  // safety fallback: full scan
        for (int k = lane; k < KCODES; k += 32) {
            float g = gumbel_bits(rbits((unsigned)n * 2048u + (unsigned)k));
            float dot = 0.0f;
            for (int d = 0; d < DDIM; d++)
                dot = __fmaf_rn(latent[n*DDIM + d], __ldg(&g_repar[k*DDIM + d]), dot);
            float dd = __fadd_rn(__fsub_rn(fn, 2.0f*dot), g_csq[k]);
            float s = __fsub_rn(g, dd);
            if (s > bestS || (s == bestS && k < bestK)) { bestS = s; bestK = k; }
        }
        for (int o = 16; o; o >>= 1) {
            float os = __shfl_xor_sync(0xffffffffu, bestS, o);
            int ok = __shfl_xor_sync(0xffffffffu, bestK, o);
            if (os > bestS || (os == bestS && ok < bestK)) { bestS = os; bestK = ok; }
        }
    }
    int idx = bestK;
    if (lane == 0) { outIdx[n] = (float)idx; atomicAdd(&g_count[idx], 1); }
    float fden = g_fden[n], cden = g_cden[idx];
    const float4* R4 = (const float4*)(g_repar + idx*DDIM);
    float4 qa = __ldg(&R4[lane*2]), qb = __ldg(&R4[lane*2 + 1]);
    float q[8] = {qa.x, qa.y, qa.z, qa.w, qb.x, qb.y, qb.z, qb.w};
    double sc = 0.0, sg = 0.0, sdq = 0.0;
    float qf[8];
#pragma unroll
    for (int i = 0; i < 8; i++) {
        float diff = __fsub_rn(f[i], q[i]);
        sc += (double)__fmul_rn(diff, diff);
        qf[i] = __fadd_rn(f[i], __fsub_rn(q[i], f[i]));
        float gd = __fsub_rn(f[i], qf[i]);
        sg += (double)__fmul_rn(gd, gd);
        sdq += (double)f[i] * (double)q[i];           // raw dot; divide once per row below
    }
    float4* O4 = (float4*)outQ;
    O4[n*64 + lane*2]     = make_float4(qf[0], qf[1], qf[2], qf[3]);
    O4[n*64 + lane*2 + 1] = make_float4(qf[4], qf[5], qf[6], qf[7]);
    for (int o = 16; o; o >>= 1) {
        sc  += __shfl_xor_sync(0xffffffffu, sc,  o);
        sg  += __shfl_xor_sync(0xffffffffu, sg,  o);
        sdq += __shfl_xor_sync(0xffffffffu, sdq, o);
    }
    if (lane == 0) {
        shc[w] = sc; shm[w] = sg;
        shg[w] = sdq / ((double)fden * (double)cden);  // cosine: one divide per row
    }
    __syncthreads();
    if (t == 0) {
        double a = 0, b = 0, c = 0;
        for (int i = 0; i < 8; i++) { a += shc[i]; b += shm[i]; c += shg[i]; }
        atomicAdd(&g_commit, a); atomicAdd(&g_gap, b); atomicAdd(&g_cos, c);
    }
}

// ---------- codebook pairwise distances: triangle tiles + FFMA2 ----------
__global__ __launch_bounds__(256) void k_cdist() {
    if (blockIdx.y > blockIdx.x) return;      // symmetric: only rb <= cb tiles
    __shared__ float As[16][132], Bs[16][132];
    __shared__ float Sr[128], Sc[128];
    __shared__ double shs[8];
    __shared__ float shmn[8];
    int t = threadIdx.x, tx = t & 15, ty = t >> 4;
    int rb = blockIdx.y * 128, cb = blockIdx.x * 128;
    double wgt = (blockIdx.y < blockIdx.x) ? 2.0 : 1.0;
    if (t < 128) Sr[t] = g_csq[rb + t]; else Sc[t-128] = g_csq[cb + t - 128];
    u64 acc2[8][4];
#pragma unroll
    for (int i = 0; i < 8; i++)
#pragma unroll
        for (int j = 0; j < 4; j++) acc2[i][j] = 0ull;
    for (int dc = 0; dc < DDIM; dc += 16) {
        __syncthreads();
#pragma unroll
        for (int i = 0; i < 8; i++) {
            int e = t + 256*i, rr = e >> 4, dd = e & 15;
            As[dd][rr] = g_repar[(rb + rr)*DDIM + dc + dd];
            Bs[dd][rr] = g_repar[(cb + rr)*DDIM + dc + dd];
        }
        __syncthreads();
#pragma unroll
        for (int kc = 0; kc < 16; kc++) {
            float4 a0 = *(const float4*)&As[kc][4*ty];
            float4 a1 = *(const float4*)&As[kc][64 + 4*ty];
            float4 b0 = *(const float4*)&Bs[kc][4*tx];
            float4 b1 = *(const float4*)&Bs[kc][64 + 4*tx];
            float av[8] = {a0.x,a0.y,a0.z,a0.w,a1.x,a1.y,a1.z,a1.w};
            u64 bv2[4] = {pk2(b0.x,b0.y), pk2(b0.z,b0.w), pk2(b1.x,b1.y), pk2(b1.z,b1.w)};
#pragma unroll
            for (int ii = 0; ii < 8; ii++) {
                u64 a2 = pk2(av[ii], av[ii]);
#pragma unroll
                for (int jj = 0; jj < 4; jj++)
                    acc2[ii][jj] = fma2(a2, bv2[jj], acc2[ii][jj]);
            }
        }
    }
    __syncthreads();
    double ls = 0.0; float lm = INFINITY;
#pragma unroll
    for (int i = 0; i < 8; i++) {
        int rl = (i < 4) ? (4*ty + i) : (64 + 4*ty + i - 4);
        int ri = rb + rl; float sr = Sr[rl];
        float accf[8];
#pragma unroll
        for (int jj = 0; jj < 4; jj++) upk2(acc2[i][jj], accf[2*jj], accf[2*jj+1]);
#pragma unroll
        for (int j = 0; j < 8; j++) {
            int cl = (j < 4) ? (4*tx + j) : (64 + 4*tx + j - 4);
            int cj = cb + cl;
            if (ri != cj) {
                float v = __fsub_rn(__fadd_rn(sr, Sc[cl]), 2.0f*accf[j]);
                v = fmaxf(v, 0.0f);
                float dist = __fsqrt_rn(v);
                ls += (double)dist; lm = fminf(lm, dist);
            }
        }
    }
    ls *= wgt;
    for (int o = 16; o; o >>= 1) {
        ls += __shfl_xor_sync(0xffffffffu, ls, o);
        lm = fminf(lm, __shfl_xor_sync(0xffffffffu, lm, o));
    }
    int lane = t & 31, w = t >> 5;
    if (lane == 0) { shs[w] = ls; shmn[w] = lm; }
    __syncthreads();
    if (t == 0) {
        double a = 0; float m = INFINITY;
        for (int i = 0; i < 8; i++) { a += shs[i]; m = fminf(m, shmn[i]); }
        atomicAdd(&g_cdsum, a);
        atomicMin(&g_cdmin_bits, __float_as_int(m));
    }
}

// ---------- scalars (1024 threads: 2 logf per thread instead of 8) ----------
__global__ __launch_bounds__(1024) void k_final(float* __restrict__ sc) {
    __shared__ double sh[32];
    int t = threadIdx.x;
    double s = 0.0;
    for (int k = t; k < KCODES; k += 1024) {
        float p = __fmul_rn((float)g_count[k], 6.103515625e-05f);
        s += (double)__fmul_rn(p, logf_rn(__fadd_rn(p, 1e-10f)));
    }
    for (int o = 16; o; o >>= 1) s += __shfl_xor_sync(0xffffffffu, s, o);
    if ((t & 31) == 0) sh[t >> 5] = s;
    __syncthreads();
    if (t == 0) {
        double ent = 0;
        for (int i = 0; i < 32; i++) ent += sh[i];
        float mse = (float)(g_commit / 4194304.0);
        sc[0] = __fmul_rn(0.25f, mse);
        sc[1] = mse;
        sc[2] = expf(-(float)ent);
        sc[3] = (float)(g_cos / 16384.0);
        sc[4] = (float)(g_cdsum / 4192256.0);
        sc[5] = __int_as_float(g_cdmin_bits);
        sc[6] = (float)sqrt(g_gap);
    }
}

extern "C" void kernel_launch(void* const* d_in, const int* in_sizes, int n_in,
                              void* d_out, int out_size) {
    const float* latent = (const float*)d_in[0];
    const float* cbk    = (const float*)d_in[1];
    const float* cmean  = (const float*)d_in[2];
    const float* cstd   = (const float*)d_in[3];
    float* out = (float*)d_out;
    float* outQ   = out;
    float* outIdx = out + NROWS*DDIM;
    float* outSc  = outIdx + NROWS;

    static cudaStream_t s_aux = 0;
    static cudaEvent_t evP = 0, evC = 0;
    if (s_aux == 0) {
        cudaStreamCreateWithFlags(&s_aux, cudaStreamNonBlocking);
        cudaEventCreateWithFlags(&evP, cudaEventDisableTiming);
        cudaEventCreateWithFlags(&evC, cudaEventDisableTiming);
    }

    // main stream: prep -> cand -> resolve -> (join) -> final
    // aux stream:  (fork after prep) cdist
    k_prep<<<2305, 256>>>(cbk, cmean, cstd, latent);
    cudaEventRecord(evP, 0);
    cudaStreamWaitEvent(s_aux, evP, 0);
    k_cdist<<<dim3(16, 16), 256, 0, s_aux>>>();
    cudaEventRecord(evC, s_aux);
    k_cand<<<NROWS, 256>>>();
    k_resolve<<<NROWS/8, 256>>>(latent, outQ, outIdx);
    cudaStreamWaitEvent(0, evC, 0);
    k_final<<<1, 1024>>>(outSc);
}

// round 15
// speedup vs baseline: 1.0971x; 1.0971x over previous
#include <cuda_runtime.h>
#include <math.h>

#define NROWS 16384
#define DDIM  256
#define KCODES 2048
#define CAP   32

typedef unsigned long long u64;

__device__ float g_repar[KCODES*DDIM];
__device__ float g_csq[KCODES];
__device__ float g_cden[KCODES];
__device__ float g_fn[NROWS];
__device__ float g_fden[NROWS];
__device__ int      g_ck[NROWS*CAP];
__device__ unsigned g_cb[NROWS*CAP];
__device__ int   g_ccnt[NROWS];
__device__ int   g_idx[NROWS];
__device__ int   g_count[KCODES];                  // zeroed each call by k_prep block 2304
__device__ int   g_cmax_bits  = 0;                 // monotone max: replay-deterministic
__device__ int   g_fnmax_bits = 0;                 // monotone max: replay-deterministic
__device__ int   g_cdmin_bits = 0x7f800000;        // monotone min: replay-deterministic
__device__ double g_cos, g_commit, g_gap, g_cdsum; // zeroed each call by k_prep block 2304

// ---------- fast-math-immune fdlibm logf (<=1 ulp) ----------
__device__ __forceinline__ float logf_rn(float x) {
    int ix = __float_as_int(x);
    int k = (ix >> 23) - 127;
    int man = ix & 0x007fffff;
    int i = (man + 0x4afb20) & 0x800000;
    float m = __int_as_float(man | (i ^ 0x3f800000));
    k += (i >> 23);
    float f = __fadd_rn(m, -1.0f);
    float s = __fdiv_rn(f, __fadd_rn(2.0f, f));
    float dk = (float)k;
    float z = __fmul_rn(s, s);
    float w = __fmul_rn(z, z);
    float t1 = __fmul_rn(w, __fmaf_rn(w, 0.24279078841f, 0.40000972152f));
    float t2 = __fmul_rn(z, __fmaf_rn(w, 0.28498786688f, 0.66666662693f));
    float R = __fadd_rn(t2, t1);
    float hfsq = __fmul_rn(0.5f, __fmul_rn(f, f));
    float a = __fmaf_rn(s, __fadd_rn(hfsq, R), __fmul_rn(dk, 9.0580006145e-06f));
    float b = __fsub_rn(__fsub_rn(hfsq, a), f);
    return __fsub_rn(__fmul_rn(dk, 0.69313812256f), b);
}

// ---------- threefry2x32, key=(0,42), natural form ----------
__device__ __forceinline__ uint2 tf_0_42(unsigned x0, unsigned x1) {
    const unsigned ks0 = 0u, ks1 = 42u, ks2 = 0x1BD11BDAu ^ 42u;
    x0 += ks0; x1 += ks1;
#define TR(r) { x0 += x1; x1 = __funnelshift_l(x1, x1, r); x1 ^= x0; }
    TR(13) TR(15) TR(26) TR(6)   x0 += ks1; x1 += ks2 + 1u;
    TR(17) TR(29) TR(16) TR(24)  x0 += ks2; x1 += ks0 + 2u;
    TR(13) TR(15) TR(26) TR(6)   x0 += ks0; x1 += ks1 + 3u;
    TR(17) TR(29) TR(16) TR(24)  x0 += ks1; x1 += ks2 + 4u;
    TR(13) TR(15) TR(26) TR(6)   x0 += ks2; x1 += ks0 + 5u;
#undef TR
    return make_uint2(x0, x1);
}

// partitionable-mode word: ctr=(0,i), fold xor
__device__ __forceinline__ unsigned rbits(unsigned i) {
    uint2 r = tf_0_42(0u, i);
    return r.x ^ r.y;
}

__device__ __forceinline__ float gumbel_bits(unsigned bits) {
    const float TINY = 1.17549435082228751e-38f;
    float f = __fadd_rn(__uint_as_float((bits >> 9) | 0x3f800000u), -1.0f);
    float u = fmaxf(TINY, __fadd_rn(f, TINY));
    return -logf_rn(-logf_rn(u));
}

// ---------- f32x2 helpers ----------
__device__ __forceinline__ u64 pk2(float lo, float hi) {
    u64 r;
    asm("mov.b64 %0, {%1, %2};" : "=l"(r) : "r"(__float_as_uint(lo)), "r"(__float_as_uint(hi)));
    return r;
}
__device__ __forceinline__ void upk2(u64 v, float& lo, float& hi) {
    unsigned a, b;
    asm("mov.b64 {%0, %1}, %2;" : "=r"(a), "=r"(b) : "l"(v));
    lo = __uint_as_float(a); hi = __uint_as_float(b);
}
__device__ __forceinline__ u64 fma2(u64 a, u64 b, u64 c) {
    u64 d;
    asm("fma.rn.f32x2 %0, %1, %2, %3;" : "=l"(d) : "l"(a), "l"(b), "l"(c));
    return d;
}

// ---------- fused prep: [0,256) codes (warp/code), [256,2304) rows, 2304 = accum reset ----------
__global__ __launch_bounds__(256) void k_prep(const float* __restrict__ cb,
                                              const float* __restrict__ cm,
                                              const float* __restrict__ cs,
                                              const float* __restrict__ latent) {
    int b = blockIdx.x, t = threadIdx.x, lane = t & 31, wp = t >> 5;
    if (b < 256) {
        int w = b * 8 + wp;            // code id
        double s = 0.0;
        for (int d = lane; d < DDIM; d += 32) {
            float r = __fadd_rn(cm[d], __fmul_rn(cs[d], cb[w*DDIM + d]));
            g_repar[w*DDIM + d] = r;
            s += (double)r * (double)r;
        }
        for (int o = 16; o; o >>= 1) s += __shfl_xor_sync(0xffffffffu, s, o);
        if (lane == 0) {
            float c = (float)s;
            g_csq[w] = c;
            g_cden[w] = fmaxf(__fsqrt_rn(c), 1e-12f);
            atomicMax(&g_cmax_bits, __float_as_int(c));
        }
    } else if (b < 2304) {
        int w = (b - 256) * 8 + wp;    // row id
        double s = 0.0;
        for (int d = lane; d < DDIM; d += 32) {
            float f = latent[w*DDIM + d];
            s += (double)f * (double)f;
        }
        for (int o = 16; o; o >>= 1) s += __shfl_xor_sync(0xffffffffu, s, o);
        if (lane == 0) {
            float v = (float)s;
            g_fn[w] = v;
            g_fden[w] = fmaxf(__fsqrt_rn(v), 1e-12f);
            atomicMax(&g_fnmax_bits, __float_as_int(v));
        }
    } else {
        for (int k = t; k < KCODES; k += 256) g_count[k] = 0;
        if (t == 0) { g_cos = 0.0; g_commit = 0.0; g_gap = 0.0; g_cdsum = 0.0; }
    }
}

// ---------- gumbel candidates: one CTA per row, bits-domain threshold ----------
__global__ __launch_bounds__(256) void k_cand() {
    __shared__ unsigned sM[8];
    __shared__ unsigned thr_s;
    __shared__ int cnt_s;
    int t = threadIdx.x;
    unsigned n = blockIdx.x;
    unsigned base = n * 2048u;
    unsigned bits[8]; unsigned m = 0;
#pragma unroll
    for (int j = 0; j < 8; j++) {
        bits[j] = rbits(base + (unsigned)t * 8u + (unsigned)j);
        m = max(m, bits[j]);
    }
    for (int o = 16; o; o >>= 1) m = max(m, __shfl_xor_sync(0xffffffffu, m, o));
    if ((t & 31) == 0) sM[t >> 5] = m;
    __syncthreads();
    if (t == 0) {
        unsigned mb = sM[0];
#pragma unroll
        for (int i = 1; i < 8; i++) mb = max(mb, sM[i]);
        float gmax = gumbel_bits(mb);
        float csqmax = __int_as_float(g_cmax_bits);
        float fnmax  = __int_as_float(g_fnmax_bits);
        float DELTA = 4.0f*__fsqrt_rn(fnmax)*__fsqrt_rn(csqmax) + csqmax + 2e-3f;
        float thr = gmax - DELTA;
        float u_thr = __expf(-__expf(-thr));
        int mant = (int)floorf(u_thr * 8388608.0f) - 64;
        thr_s = (mant < 0) ? 0u : ((unsigned)mant << 9);
        cnt_s = 0;
    }
    __syncthreads();
    unsigned thr = thr_s;
#pragma unroll
    for (int j = 0; j < 8; j++) {
        if (bits[j] >= thr) {
            int pos = atomicAdd(&cnt_s, 1);
            if (pos < CAP) { g_ck[n*CAP+pos] = t*8+j; g_cb[n*CAP+pos] = bits[j]; }
        }
    }
    __syncthreads();
    if (t == 0) g_ccnt[n] = cnt_s;
}

// ---------- resolve indices only (warp per row); cnt==1 fast path avoids latent ----------
__global__ __launch_bounds__(256) void k_residx(const float* __restrict__ latent,
                                                float* __restrict__ outIdx) {
    int t = threadIdx.x, lane = t & 31, w = t >> 5;
    int n = blockIdx.x * 8 + w;
    int cnt = g_ccnt[n];
    if (cnt == 1) {                     // ~98-99% of rows: winner is the single candidate
        if (lane == 0) {
            int idx = g_ck[n*CAP];
            g_idx[n] = idx;
            outIdx[n] = (float)idx;
            atomicAdd(&g_count[idx], 1);
        }
        return;
    }
    const float4* L4 = (const float4*)latent;
    float4 fa = L4[n*64 + lane*2], fb = L4[n*64 + lane*2 + 1];
    float fn = g_fn[n];
    float bestS = -INFINITY; int bestK = 0x7fffffff;
    if (cnt <= CAP) {
        for (int j = 0; j < cnt; j++) {
            int k = g_ck[n*CAP + j];
            float g = gumbel_bits(g_cb[n*CAP + j]);
            const float4* R4 = (const float4*)(g_repar + k*DDIM);
            float4 ca = __ldg(&R4[lane*2]), cb4 = __ldg(&R4[lane*2 + 1]);
            float dot = 0.0f;
            dot = __fmaf_rn(fa.x, ca.x, dot);  dot = __fmaf_rn(fa.y, ca.y, dot);
            dot = __fmaf_rn(fa.z, ca.z, dot);  dot = __fmaf_rn(fa.w, ca.w, dot);
            dot = __fmaf_rn(fb.x, cb4.x, dot); dot = __fmaf_rn(fb.y, cb4.y, dot);
            dot = __fmaf_rn(fb.z, cb4.z, dot); dot = __fmaf_rn(fb.w, cb4.w, dot);
            for (int o = 16; o; o >>= 1) dot = __fadd_rn(dot, __shfl_xor_sync(0xffffffffu, dot, o));
            float d = __fadd_rn(__fsub_rn(fn, 2.0f*dot), g_csq[k]);
            float s = __fsub_rn(g, d);
            if (s > bestS || (s == bestS && k < bestK)) { bestS = s; bestK = k; }
        }
    } else {  // safety fallback: full scan (never expected)
        for (int k = lane; k < KCODES; k += 32) {
            float g = gumbel_bits(rbits((unsigned)n * 2048u + (unsigned)k));
            float dot = 0.0f;
            for (int d = 0; d < DDIM; d++)
                dot = __fmaf_rn(latent[n*DDIM + d], __ldg(&g_repar[k*DDIM + d]), dot);
            float dd = __fadd_rn(__fsub_rn(fn, 2.0f*dot), g_csq[k]);
            float s = __fsub_rn(g, dd);
            if (s > bestS || (s == bestS && k < bestK)) { bestS = s; bestK = k; }
        }
        for (int o = 16; o; o >>= 1) {
            float os = __shfl_xor_sync(0xffffffffu, bestS, o);
            int ok = __shfl_xor_sync(0xffffffffu, bestK, o);
            if (os > bestS || (os == bestS && ok < bestK)) { bestS = os; bestK = ok; }
        }
    }
    if (lane == 0) {
        g_idx[n] = bestK;
        outIdx[n] = (float)bestK;
        atomicAdd(&g_count[bestK], 1);
    }
}

// ---------- streaming epilogue: quantized + commit/gap/cos (warp per row) ----------
__global__ __launch_bounds__(256) void k_epi(const float* __restrict__ latent,
                                             float* __restrict__ outQ) {
    __shared__ double shc[8], shm[8], shg[8];
    int t = threadIdx.x, lane = t & 31, w = t >> 5;
    int n = blockIdx.x * 8 + w;
    int idx = g_idx[n];
    const float4* L4 = (const float4*)latent;
    const float4* R4 = (const float4*)(g_repar + idx*DDIM);
    float4 fa = L4[n*64 + lane*2], fb = L4[n*64 + lane*2 + 1];
    float4 qa = __ldg(&R4[lane*2]), qb = __ldg(&R4[lane*2 + 1]);
    float f[8] = {fa.x, fa.y, fa.z, fa.w, fb.x, fb.y, fb.z, fb.w};
    float q[8] = {qa.x, qa.y, qa.z, qa.w, qb.x, qb.y, qb.z, qb.w};
    float fden = g_fden[n], cden = g_cden[idx];
    double sc = 0.0, sg = 0.0;
    float sdq = 0.0f;
    float qf[8];
#pragma unroll
    for (int i = 0; i < 8; i++) {
        float diff = __fsub_rn(f[i], q[i]);
        sc += (double)__fmul_rn(diff, diff);
        qf[i] = __fadd_rn(f[i], __fsub_rn(q[i], f[i]));    // STE value
        float gd = __fsub_rn(f[i], qf[i]);
        sg += (double)__fmul_rn(gd, gd);
        sdq = __fmaf_rn(f[i], q[i], sdq);
    }
    float4* O4 = (float4*)outQ;
    O4[n*64 + lane*2]     = make_float4(qf[0], qf[1], qf[2], qf[3]);
    O4[n*64 + lane*2 + 1] = make_float4(qf[4], qf[5], qf[6], qf[7]);
    for (int o = 16; o; o >>= 1) {
        sc  += __shfl_xor_sync(0xffffffffu, sc,  o);
        sg  += __shfl_xor_sync(0xffffffffu, sg,  o);
        sdq += __shfl_xor_sync(0xffffffffu, sdq, o);
    }
    if (lane == 0) {
        shc[w] = sc; shm[w] = sg;
        shg[w] = (double)sdq / ((double)fden * (double)cden);  // one divide per row
    }
    __syncthreads();
    if (t == 0) {
        double a = 0, b = 0, c = 0;
#pragma unroll
        for (int i = 0; i < 8; i++) { a += shc[i]; b += shm[i]; c += shg[i]; }
        atomicAdd(&g_commit, a); atomicAdd(&g_gap, b); atomicAdd(&g_cos, c);
    }
}

// ---------- codebook pairwise distances: triangle tiles + FFMA2 ----------
__global__ __launch_bounds__(256) void k_cdist() {
    if (blockIdx.y > blockIdx.x) return;      // symmetric: only rb <= cb tiles
    __shared__ float As[16][132], Bs[16][132];
    __shared__ float Sr[128], Sc[128];
    __shared__ double shs[8];
    __shared__ float shmn[8];
    int t = threadIdx.x, tx = t & 15, ty = t >> 4;
    int rb = blockIdx.y * 128, cb = blockIdx.x * 128;
    double wgt = (blockIdx.y < blockIdx.x) ? 2.0 : 1.0;
    if (t < 128) Sr[t] = g_csq[rb + t]; else Sc[t-128] = g_csq[cb + t - 128];
    u64 acc2[8][4];
#pragma unroll
    for (int i = 0; i < 8; i++)
#pragma unroll
        for (int j = 0; j < 4; j++) acc2[i][j] = 0ull;
    for (int dc = 0; dc < DDIM; dc += 16) {
        __syncthreads();
#pragma unroll
        for (int i = 0; i < 8; i++) {
            int e = t + 256*i, rr = e >> 4, dd = e & 15;
            As[dd][rr] = g_repar[(rb + rr)*DDIM + dc + dd];
            Bs[dd][rr] = g_repar[(cb + rr)*DDIM + dc + dd];
        }
        __syncthreads();
#pragma unroll
        for (int kc = 0; kc < 16; kc++) {
            float4 a0 = *(const float4*)&As[kc][4*ty];
            float4 a1 = *(const float4*)&As[kc][64 + 4*ty];
            float4 b0 = *(const float4*)&Bs[kc][4*tx];
            float4 b1 = *(const float4*)&Bs[kc][64 + 4*tx];
            float av[8] = {a0.x,a0.y,a0.z,a0.w,a1.x,a1.y,a1.z,a1.w};
            u64 bv2[4] = {pk2(b0.x,b0.y), pk2(b0.z,b0.w), pk2(b1.x,b1.y), pk2(b1.z,b1.w)};
#pragma unroll
            for (int ii = 0; ii < 8; ii++) {
                u64 a2 = pk2(av[ii], av[ii]);
#pragma unroll
                for (int jj = 0; jj < 4; jj++)
                    acc2[ii][jj] = fma2(a2, bv2[jj], acc2[ii][jj]);
            }
        }
    }
    __syncthreads();
    double ls = 0.0; float lm = INFINITY;
#pragma unroll
    for (int i = 0; i < 8; i++) {
        int rl = (i < 4) ? (4*ty + i) : (64 + 4*ty + i - 4);
        int ri = rb + rl; float sr = Sr[rl];
        float accf[8];
#pragma unroll
        for (int jj = 0; jj < 4; jj++) upk2(acc2[i][jj], accf[2*jj], accf[2*jj+1]);
#pragma unroll
        for (int j = 0; j < 8; j++) {
            int cl = (j < 4) ? (4*tx + j) : (64 + 4*tx + j - 4);
            int cj = cb + cl;
            if (ri != cj) {
                float v = __fsub_rn(__fadd_rn(sr, Sc[cl]), 2.0f*accf[j]);
                v = fmaxf(v, 0.0f);
                float dist = __fsqrt_rn(v);
                ls += (double)dist; lm = fminf(lm, dist);
            }
        }
    }
    ls *= wgt;
    for (int o = 16; o; o >>= 1) {
        ls += __shfl_xor_sync(0xffffffffu, ls, o);
        lm = fminf(lm, __shfl_xor_sync(0xffffffffu, lm, o));
    }
    int lane = t & 31, w = t >> 5;
    if (lane == 0) { shs[w] = ls; shmn[w] = lm; }
    __syncthreads();
    if (t == 0) {
        double a = 0; float m = INFINITY;
        for (int i = 0; i < 8; i++) { a += shs[i]; m = fminf(m, shmn[i]); }
        atomicAdd(&g_cdsum, a);
        atomicMin(&g_cdmin_bits, __float_as_int(m));
    }
}

// ---------- scalars ----------
__global__ __launch_bounds__(1024) void k_final(float* __restrict__ sc) {
    __shared__ double sh[32];
    int t = threadIdx.x;
    double s = 0.0;
    for (int k = t; k < KCODES; k += 1024) {
        float p = __fmul_rn((float)g_count[k], 6.103515625e-05f);
        s += (double)__fmul_rn(p, logf_rn(__fadd_rn(p, 1e-10f)));
    }
    for (int o = 16; o; o >>= 1) s += __shfl_xor_sync(0xffffffffu, s, o);
    if ((t & 31) == 0) sh[t >> 5] = s;
    __syncthreads();
    if (t == 0) {
        double ent = 0;
        for (int i = 0; i < 32; i++) ent += sh[i];
        float mse = (float)(g_commit / 4194304.0);
        sc[0] = __fmul_rn(0.25f, mse);
        sc[1] = mse;
        sc[2] = expf(-(float)ent);
        sc[3] = (float)(g_cos / 16384.0);
        sc[4] = (float)(g_cdsum / 4192256.0);
        sc[5] = __int_as_float(g_cdmin_bits);
        sc[6] = (float)sqrt(g_gap);
    }
}

extern "C" void kernel_launch(void* const* d_in, const int* in_sizes, int n_in,
                              void* d_out, int out_size) {
    const float* latent = (const float*)d_in[0];
    const float* cbk    = (const float*)d_in[1];
    const float* cmean  = (const float*)d_in[2];
    const float* cstd   = (const float*)d_in[3];
    float* out = (float*)d_out;
    float* outQ   = out;
    float* outIdx = out + NROWS*DDIM;
    float* outSc  = outIdx + NROWS;

    static cudaStream_t s_aux = 0;
    static cudaEvent_t evP = 0, evC = 0;
    if (s_aux == 0) {
        cudaStreamCreateWithFlags(&s_aux, cudaStreamNonBlocking);
        cudaEventCreateWithFlags(&evP, cudaEventDisableTiming);
        cudaEventCreateWithFlags(&evC, cudaEventDisableTiming);
    }

    // main stream: prep -> cand -> residx -> epi -> (join) -> final
    // aux stream:  (fork after prep) cdist
    k_prep<<<2305, 256>>>(cbk, cmean, cstd, latent);
    cudaEventRecord(evP, 0);
    cudaStreamWaitEvent(s_aux, evP, 0);
    k_cdist<<<dim3(16, 16), 256, 0, s_aux>>>();
    cudaEventRecord(evC, s_aux);
    k_cand<<<NROWS, 256>>>();
    k_residx<<<NROWS/8, 256>>>(latent, outIdx);
    k_epi<<<NROWS/8, 256>>>(latent, outQ);
    cudaStreamWaitEvent(0, evC, 0);
    k_final<<<1, 1024>>>(outSc);
}